// round 13
// baseline (speedup 1.0000x reference)
#include <cuda_runtime.h>
#include <cstddef>

#define NA 20000
#define NP 40000
#define EE 400000
#define HID 128
#define NCLS 16

// ----------------------------- scratch (static device globals) -------------------
__device__ float g_Wc[64 * HID];            // Wa @ proj_w[0,author]  (folded)
__device__ float g_aggA[NA * HID];
__device__ float g_xa[NA * HID];
__device__ float g_xp[NP * HID];
__device__ float g_aggP0[NP * HID];
__device__ float g_aggP1[NP * HID];
__device__ float g_sa0[NA * 8];
__device__ float g_sa1[NA * 8];
__device__ float g_sp0[NP * 8];
__device__ float g_sp1[NP * 8];
__device__ float g_sp2[NP * 8];
__device__ float g_sp3[NP * 8];
__device__ float g_colsum[2 * HID];
__device__ float g_attn0[2];
__device__ float g_attn1[2];
__device__ float g_zb[HID];
__device__ int g_rp_w[NP + 1];
__device__ int g_rp_wb[NA + 1];
__device__ int g_rp_c[NP + 1];
__device__ int g_src_w[EE];
__device__ int g_src_wb[EE];
__device__ int g_src_c[EE];
__device__ int g_cnt[NP + NA + NP];
__device__ int g_aux[3 * 256];

// ----------------------------- CSR build (R11-proven) -----------------------------
struct H3 { const int* dst[3]; int* cnt[3]; };
__global__ void hist3_k(H3 p)
{
    const int y = blockIdx.y;
    const int e = blockIdx.x * blockDim.x + threadIdx.x;
    if (e < EE) atomicAdd(&p.cnt[y][__ldg(&p.dst[y][e])], 1);
}

struct SC3 { const int* cnt[3]; int* rowptr[3]; int* aux[3]; int n[3]; };
__global__ void scan_blk3_k(SC3 p)
{
    const int y = blockIdx.y;
    const int n = p.n[y];
    if (blockIdx.x * 256 >= n) return;
    __shared__ int s[256];
    const int tid = threadIdx.x;
    const int i = blockIdx.x * 256 + tid;
    s[tid] = (i < n) ? p.cnt[y][i] : 0;
    __syncthreads();
#pragma unroll
    for (int off = 1; off < 256; off <<= 1) {
        int t = (tid >= off) ? s[tid - off] : 0;
        __syncthreads();
        s[tid] += t;
        __syncthreads();
    }
    if (i < n) p.rowptr[y][i + 1] = s[tid];
    if (tid == 255) p.aux[y][blockIdx.x] = s[255];
}

struct SA3 { int* aux[3]; int nb[3]; };
__global__ void scan_aux3_k(SA3 p)
{
    const int y = blockIdx.x;
    const int nb = p.nb[y];
    __shared__ int s[256];
    const int tid = threadIdx.x;
    int v = (tid < nb) ? p.aux[y][tid] : 0;
    s[tid] = v;
    __syncthreads();
#pragma unroll
    for (int off = 1; off < 256; off <<= 1) {
        int t = (tid >= off) ? s[tid - off] : 0;
        __syncthreads();
        s[tid] += t;
        __syncthreads();
    }
    if (tid < nb) p.aux[y][tid] = s[tid] - v;
}

struct AD3 { int* rowptr[3]; const int* aux[3]; int n[3]; };
__global__ void scan_add3_k(AD3 p)
{
    const int y = blockIdx.y;
    const int i = blockIdx.x * blockDim.x + threadIdx.x;
    if (i < p.n[y]) p.rowptr[y][i + 1] += p.aux[y][i >> 8];
    if (i == 0) p.rowptr[y][0] = 0;
}

struct S3 { const int* ei[3]; const int* rowptr[3]; int* cursor[3]; int* srcs[3]; };
__global__ void scatter3_k(S3 p)
{
    const int y = blockIdx.y;
    const int e = blockIdx.x * blockDim.x + threadIdx.x;
    if (e >= EE) return;
    const int si = __ldg(&p.ei[y][e]);
    const int di = __ldg(&p.ei[y][EE + e]);
    const int pos = atomicAdd(&p.cursor[y][di], 1);
    p.srcs[y][p.rowptr[y][di] + pos] = si;
}

// ----------------------------- fused CSR aggregation -------------------------------
// AG2: up to 2 edge types (same ndst) in one launch via blockIdx.y.
struct AG2 {
    const int* rowptr[2]; const int* srcs[2];
    const float* asrc[2]; const float* adst[2];
    const float* xh[2]; float* agg[2];
};

__global__ __launch_bounds__(256)
void agg2_k(AG2 p, int ndst)
{
    const int y = blockIdx.y;
    const int w = (blockIdx.x * blockDim.x + threadIdx.x) >> 5;
    if (w >= ndst) return;
    const int lane = threadIdx.x & 31;
    const int h = lane >> 2;
    const int start = __ldg(&p.rowptr[y][w]);
    const int end   = __ldg(&p.rowptr[y][w + 1]);
    const float ad = __ldg(&p.adst[y][(size_t)w * 8 + h]);
    const int* __restrict__ srcs = p.srcs[y];
    const float* __restrict__ asrc = p.asrc[y];
    const float4* __restrict__ xh4 = (const float4*)p.xh[y];

    float4 acc = make_float4(0.f, 0.f, 0.f, 0.f);
    float den = 0.f;
    for (int p0 = start; p0 < end; p0 += 32) {
        const int nedge = min(32, end - p0);
        const int myidx = (lane < nedge) ? __ldg(&srcs[p0 + lane]) : 0;
#pragma unroll 4
        for (int j = 0; j < nedge; j++) {
            const int si = __shfl_sync(0xffffffffu, myidx, j);
            float a = __ldg(&asrc[(size_t)si * 8 + h]) + ad;
            a = (a >= 0.f) ? a : 0.2f * a;
            const float e = __expf(a);
            den += e;
            float4 v = __ldg(xh4 + (size_t)si * 32 + lane);
            acc.x = fmaf(e, v.x, acc.x);
            acc.y = fmaf(e, v.y, acc.y);
            acc.z = fmaf(e, v.z, acc.z);
            acc.w = fmaf(e, v.w, acc.w);
        }
    }
    const float inv = 1.f / (den + 1e-16f);
    acc.x *= inv; acc.y *= inv; acc.z *= inv; acc.w *= inv;
    ((float4*)p.agg[y])[(size_t)w * 32 + lane] = acc;
}

// single-type variant (author written_by)
__global__ __launch_bounds__(256)
void agg_csr_k(const int* __restrict__ rowptr, const int* __restrict__ srcs,
               const float* __restrict__ asrc, const float* __restrict__ adst,
               const float* __restrict__ xh, float* __restrict__ agg, int ndst)
{
    const int w = (blockIdx.x * blockDim.x + threadIdx.x) >> 5;
    if (w >= ndst) return;
    const int lane = threadIdx.x & 31;
    const int h = lane >> 2;
    const int start = __ldg(&rowptr[w]);
    const int end   = __ldg(&rowptr[w + 1]);
    const float ad = __ldg(&adst[(size_t)w * 8 + h]);

    float4 acc = make_float4(0.f, 0.f, 0.f, 0.f);
    float den = 0.f;
    for (int p0 = start; p0 < end; p0 += 32) {
        const int nedge = min(32, end - p0);
        const int myidx = (lane < nedge) ? __ldg(&srcs[p0 + lane]) : 0;
#pragma unroll 4
        for (int j = 0; j < nedge; j++) {
            const int si = __shfl_sync(0xffffffffu, myidx, j);
            float a = __ldg(&asrc[(size_t)si * 8 + h]) + ad;
            a = (a >= 0.f) ? a : 0.2f * a;
            const float e = __expf(a);
            den += e;
            float4 v = __ldg(((const float4*)xh) + (size_t)si * 32 + lane);
            acc.x = fmaf(e, v.x, acc.x);
            acc.y = fmaf(e, v.y, acc.y);
            acc.z = fmaf(e, v.z, acc.z);
            acc.w = fmaf(e, v.w, acc.w);
        }
    }
    const float inv = 1.f / (den + 1e-16f);
    acc.x *= inv; acc.y *= inv; acc.z *= inv; acc.w *= inv;
    ((float4*)agg)[(size_t)w * 32 + lane] = acc;
}

// ----------------------------- tf32 mma helpers ------------------------------------
__device__ __forceinline__ unsigned f2tf(float f) {
    unsigned u;
    asm("cvt.rna.tf32.f32 %0, %1;" : "=r"(u) : "f"(f));
    return u;
}
__device__ __forceinline__ float tfbits(float f) {
    return __uint_as_float(f2tf(f));
}
__device__ __forceinline__ void mma_tf32(float4& d, const unsigned* a,
                                         unsigned b0, unsigned b1) {
    asm volatile(
        "mma.sync.aligned.m16n8k8.row.col.f32.tf32.tf32.f32 "
        "{%0,%1,%2,%3}, {%4,%5,%6,%7}, {%8,%9}, {%0,%1,%2,%3};"
        : "+f"(d.x), "+f"(d.y), "+f"(d.z), "+f"(d.w)
        : "r"(a[0]), "r"(a[1]), "r"(a[2]), "r"(a[3]), "r"(b0), "r"(b1));
}

// ----------------------------- GEMM (tf32, k-tile 16; R11-proven) ------------------
template <int TANH, int RELUA, int COMBINE>
__global__ __launch_bounds__(256)
void sgemm_k(const float* __restrict__ A0, const float* __restrict__ A1,
             const float* __restrict__ attnp,
             const float* __restrict__ B, const float* __restrict__ bias,
             float* __restrict__ C, float* __restrict__ colsum, int M, int K)
{
    __shared__ alignas(16) float As[16][136];
    __shared__ alignas(16) float Bs[16][136];

    const float* A = (TANH && blockIdx.y) ? A1 : A0;
    float* cs = TANH ? colsum + blockIdx.y * 128 : colsum;

    const int tid = threadIdx.x;
    const int lane = tid & 31;
    const int warp = tid >> 5;
    const int wm = warp & 3;
    const int wn = warp >> 2;
    const int g = lane >> 2;
    const int t = lane & 3;
    const int block_row = blockIdx.x * 128;

    const int a_row = tid >> 1;
    const int a_col = (tid & 1) * 8;
    const int b_row = tid >> 4;
    const int b_col = (tid & 15) * 8;

    float ca0 = 0.f, ca1 = 0.f;
    if constexpr (COMBINE) { ca0 = __ldg(&attnp[0]); ca1 = __ldg(&attnp[1]); }

    const int gr = block_row + a_row;
    const bool arow_ok = (gr < M);

    float4 d[2][8];
#pragma unroll
    for (int i = 0; i < 2; i++)
#pragma unroll
        for (int j = 0; j < 8; j++) d[i][j] = make_float4(0.f, 0.f, 0.f, 0.f);

    float4 av0, av1, bv0, bv1;

    auto loadA = [&](int k0, float4& o0, float4& o1) {
        o0 = make_float4(0.f, 0.f, 0.f, 0.f);
        o1 = o0;
        if (arow_ok) {
            o0 = *(const float4*)(A + (size_t)gr * K + k0 + a_col);
            o1 = *(const float4*)(A + (size_t)gr * K + k0 + a_col + 4);
            if constexpr (COMBINE) {
                float4 w0 = *(const float4*)(A1 + (size_t)gr * K + k0 + a_col);
                float4 w1 = *(const float4*)(A1 + (size_t)gr * K + k0 + a_col + 4);
                o0.x = ca0 * fmaxf(o0.x, 0.f) + ca1 * fmaxf(w0.x, 0.f);
                o0.y = ca0 * fmaxf(o0.y, 0.f) + ca1 * fmaxf(w0.y, 0.f);
                o0.z = ca0 * fmaxf(o0.z, 0.f) + ca1 * fmaxf(w0.z, 0.f);
                o0.w = ca0 * fmaxf(o0.w, 0.f) + ca1 * fmaxf(w0.w, 0.f);
                o1.x = ca0 * fmaxf(o1.x, 0.f) + ca1 * fmaxf(w1.x, 0.f);
                o1.y = ca0 * fmaxf(o1.y, 0.f) + ca1 * fmaxf(w1.y, 0.f);
                o1.z = ca0 * fmaxf(o1.z, 0.f) + ca1 * fmaxf(w1.z, 0.f);
                o1.w = ca0 * fmaxf(o1.w, 0.f) + ca1 * fmaxf(w1.w, 0.f);
            } else if constexpr (RELUA || TANH) {
                o0.x = fmaxf(o0.x, 0.f); o0.y = fmaxf(o0.y, 0.f);
                o0.z = fmaxf(o0.z, 0.f); o0.w = fmaxf(o0.w, 0.f);
                o1.x = fmaxf(o1.x, 0.f); o1.y = fmaxf(o1.y, 0.f);
                o1.z = fmaxf(o1.z, 0.f); o1.w = fmaxf(o1.w, 0.f);
            }
        }
    };

    loadA(0, av0, av1);
    bv0 = *(const float4*)(B + (size_t)b_row * 128 + b_col);
    bv1 = *(const float4*)(B + (size_t)b_row * 128 + b_col + 4);

    for (int k0 = 0; k0 < K; k0 += 16) {
        As[a_col + 0][a_row] = tfbits(av0.x);
        As[a_col + 1][a_row] = tfbits(av0.y);
        As[a_col + 2][a_row] = tfbits(av0.z);
        As[a_col + 3][a_row] = tfbits(av0.w);
        As[a_col + 4][a_row] = tfbits(av1.x);
        As[a_col + 5][a_row] = tfbits(av1.y);
        As[a_col + 6][a_row] = tfbits(av1.z);
        As[a_col + 7][a_row] = tfbits(av1.w);
        Bs[b_row][b_col + 0] = tfbits(bv0.x);
        Bs[b_row][b_col + 1] = tfbits(bv0.y);
        Bs[b_row][b_col + 2] = tfbits(bv0.z);
        Bs[b_row][b_col + 3] = tfbits(bv0.w);
        Bs[b_row][b_col + 4] = tfbits(bv1.x);
        Bs[b_row][b_col + 5] = tfbits(bv1.y);
        Bs[b_row][b_col + 6] = tfbits(bv1.z);
        Bs[b_row][b_col + 7] = tfbits(bv1.w);
        __syncthreads();

        if (k0 + 16 < K) {
            loadA(k0 + 16, av0, av1);
            bv0 = *(const float4*)(B + (size_t)(k0 + 16 + b_row) * 128 + b_col);
            bv1 = *(const float4*)(B + (size_t)(k0 + 16 + b_row) * 128 + b_col + 4);
        }

#pragma unroll
        for (int kk = 0; kk < 16; kk += 8) {
            unsigned au[2][4];
#pragma unroll
            for (int mi = 0; mi < 2; mi++) {
                const int rb = wm * 32 + mi * 16 + g;
                au[mi][0] = __float_as_uint(As[kk + t][rb]);
                au[mi][1] = __float_as_uint(As[kk + t][rb + 8]);
                au[mi][2] = __float_as_uint(As[kk + t + 4][rb]);
                au[mi][3] = __float_as_uint(As[kk + t + 4][rb + 8]);
            }
#pragma unroll
            for (int ni = 0; ni < 8; ni++) {
                const int nb = wn * 64 + ni * 8 + g;
                const unsigned b0 = __float_as_uint(Bs[kk + t][nb]);
                const unsigned b1 = __float_as_uint(Bs[kk + t + 4][nb]);
                mma_tf32(d[0][ni], au[0], b0, b1);
                mma_tf32(d[1][ni], au[1], b0, b1);
            }
        }
        __syncthreads();
    }

    float2 bb[8];
#pragma unroll
    for (int ni = 0; ni < 8; ni++) {
        const int c = wn * 64 + ni * 8 + t * 2;
        bb[ni] = make_float2(__ldg(&bias[c]), __ldg(&bias[c + 1]));
    }

    if constexpr (TANH) {
        __shared__ float red[128];
        if (tid < 128) red[tid] = 0.f;
        __syncthreads();
#pragma unroll
        for (int ni = 0; ni < 8; ni++) {
            const int c = wn * 64 + ni * 8 + t * 2;
            float sx = 0.f, sy = 0.f;
#pragma unroll
            for (int mi = 0; mi < 2; mi++) {
                const int r0 = block_row + wm * 32 + mi * 16 + g;
                const int r1 = r0 + 8;
                if (r0 < M) {
                    sx += tanhf(d[mi][ni].x + bb[ni].x);
                    sy += tanhf(d[mi][ni].y + bb[ni].y);
                }
                if (r1 < M) {
                    sx += tanhf(d[mi][ni].z + bb[ni].x);
                    sy += tanhf(d[mi][ni].w + bb[ni].y);
                }
            }
            atomicAdd(&red[c], sx);
            atomicAdd(&red[c + 1], sy);
        }
        __syncthreads();
        if (tid < 128) atomicAdd(&cs[tid], red[tid]);
    } else {
#pragma unroll
        for (int mi = 0; mi < 2; mi++) {
            const int r0 = block_row + wm * 32 + mi * 16 + g;
            const int r1 = r0 + 8;
#pragma unroll
            for (int ni = 0; ni < 8; ni++) {
                const int c = wn * 64 + ni * 8 + t * 2;
                if (r0 < M)
                    *(float2*)(C + (size_t)r0 * 128 + c) =
                        make_float2(d[mi][ni].x + bb[ni].x, d[mi][ni].y + bb[ni].y);
                if (r1 < M)
                    *(float2*)(C + (size_t)r1 * 128 + c) =
                        make_float2(d[mi][ni].z + bb[ni].x, d[mi][ni].w + bb[ni].y);
            }
        }
    }
}

// ----------------------------- multi attention scores ------------------------------
struct MS { const float* att[4]; float* out[4]; int nsc; };

__global__ void att_multi_k(const float* __restrict__ xh, MS ms, int N)
{
    const int t = blockIdx.x * blockDim.x + threadIdx.x;
    if (t >= N * 8) return;
    const int n = t >> 3, h = t & 7;
    const float4* xr = (const float4*)(xh + (size_t)n * HID + h * 16);
    float4 x0 = __ldg(&xr[0]), x1 = __ldg(&xr[1]);
    float4 x2 = __ldg(&xr[2]), x3 = __ldg(&xr[3]);
#pragma unroll
    for (int s = 0; s < 4; s++) {
        if (s < ms.nsc) {
            const float4* ar = (const float4*)(ms.att[s] + h * 16);
            float4 a0 = __ldg(&ar[0]), a1 = __ldg(&ar[1]);
            float4 a2 = __ldg(&ar[2]), a3 = __ldg(&ar[3]);
            float r = x0.x * a0.x + x0.y * a0.y + x0.z * a0.z + x0.w * a0.w
                    + x1.x * a1.x + x1.y * a1.y + x1.z * a1.z + x1.w * a1.w
                    + x2.x * a2.x + x2.y * a2.y + x2.z * a2.z + x2.w * a2.w
                    + x3.x * a3.x + x3.y * a3.y + x3.z * a3.z + x3.w * a3.w;
            ms.out[s][t] = r;
        }
    }
}

// ----------------------------- semantic attention weights (M=2) --------------------
__global__ void sem_attn_k(const float* __restrict__ colsum, const float* __restrict__ q,
                           float* __restrict__ attn)
{
    __shared__ float r0[128], r1[128];
    const int t = threadIdx.x;
    const float qv = q[t];
    r0[t] = qv * colsum[t];
    r1[t] = qv * colsum[128 + t];
    __syncthreads();
    for (int s = 64; s > 0; s >>= 1) {
        if (t < s) { r0[t] += r0[t + s]; r1[t] += r1[t + s]; }
        __syncthreads();
    }
    if (t == 0) {
        const float s0 = r0[0] / (float)NP;
        const float s1 = r1[0] / (float)NP;
        const float m = fmaxf(s0, s1);
        const float e0 = __expf(s0 - m), e1 = __expf(s1 - m);
        const float inv = 1.f / (e0 + e1);
        attn[0] = e0 * inv;
        attn[1] = e1 * inv;
    }
}

// ----------------------------- final linear (fused layer-1 combine + relu) ---------
__global__ __launch_bounds__(256)
void final_lin_k(const float* __restrict__ s0, const float* __restrict__ s1,
                 const float* __restrict__ attn, const float* __restrict__ W,
                 const float* __restrict__ b, float* __restrict__ out)
{
    __shared__ float Ws[128 * NCLS];
    for (int i = threadIdx.x; i < 128 * NCLS; i += blockDim.x) Ws[i] = W[i];
    __syncthreads();
    const int n = blockIdx.x * blockDim.x + threadIdx.x;
    if (n >= NP) return;
    const float a0 = __ldg(&attn[0]);
    const float a1 = __ldg(&attn[1]);
    float acc[NCLS];
#pragma unroll
    for (int c = 0; c < NCLS; c++) acc[c] = __ldg(&b[c]);
    const float4* x0 = (const float4*)(s0 + (size_t)n * 128);
    const float4* x1 = (const float4*)(s1 + (size_t)n * 128);
#pragma unroll
    for (int k4 = 0; k4 < 32; k4++) {
        float4 u = __ldg(&x0[k4]);
        float4 v = __ldg(&x1[k4]);
        const float xs[4] = {
            a0 * fmaxf(u.x, 0.f) + a1 * fmaxf(v.x, 0.f),
            a0 * fmaxf(u.y, 0.f) + a1 * fmaxf(v.y, 0.f),
            a0 * fmaxf(u.z, 0.f) + a1 * fmaxf(v.z, 0.f),
            a0 * fmaxf(u.w, 0.f) + a1 * fmaxf(v.w, 0.f)};
#pragma unroll
        for (int uu = 0; uu < 4; uu++) {
            const int k = k4 * 4 + uu;
#pragma unroll
            for (int c = 0; c < NCLS; c++)
                acc[c] = fmaf(xs[uu], Ws[k * NCLS + c], acc[c]);
        }
    }
    float4* op = (float4*)(out + (size_t)n * NCLS);
#pragma unroll
    for (int c4 = 0; c4 < 4; c4++)
        op[c4] = make_float4(acc[c4 * 4], acc[c4 * 4 + 1], acc[c4 * 4 + 2], acc[c4 * 4 + 3]);
}

// ----------------------------- host orchestration ----------------------------------
extern "C" void kernel_launch(void* const* d_in, const int* in_sizes, int n_in,
                              void* d_out, int out_size)
{
    const float* x_author = (const float*)d_in[0];
    const float* x_paper  = (const float*)d_in[1];
    const float* Wa       = (const float*)d_in[2];
    const float* proj_w   = (const float*)d_in[3];
    const float* proj_b   = (const float*)d_in[4];
    const float* att_src  = (const float*)d_in[5];
    const float* att_dst  = (const float*)d_in[6];
    const float* klin_w   = (const float*)d_in[7];
    const float* klin_b   = (const float*)d_in[8];
    const float* q        = (const float*)d_in[9];
    const float* lin_w    = (const float*)d_in[10];
    const float* lin_b    = (const float*)d_in[11];
    const int*   ei_w     = (const int*)d_in[12];
    const int*   ei_wb    = (const int*)d_in[13];
    const int*   ei_c     = (const int*)d_in[14];
    float* out = (float*)d_out;

    float *Wc, *aggA, *xa, *xp, *aggP0, *aggP1;
    float *sa0, *sa1, *sp0, *sp1, *sp2, *sp3, *colsum, *attn0, *attn1, *zb;
    int *rp_w, *rp_wb, *rp_c, *src_w, *src_wb, *src_c, *cnt, *aux;
    cudaGetSymbolAddress((void**)&Wc, g_Wc);
    cudaGetSymbolAddress((void**)&aggA, g_aggA);
    cudaGetSymbolAddress((void**)&xa, g_xa);
    cudaGetSymbolAddress((void**)&xp, g_xp);
    cudaGetSymbolAddress((void**)&aggP0, g_aggP0);
    cudaGetSymbolAddress((void**)&aggP1, g_aggP1);
    cudaGetSymbolAddress((void**)&sa0, g_sa0);
    cudaGetSymbolAddress((void**)&sa1, g_sa1);
    cudaGetSymbolAddress((void**)&sp0, g_sp0);
    cudaGetSymbolAddress((void**)&sp1, g_sp1);
    cudaGetSymbolAddress((void**)&sp2, g_sp2);
    cudaGetSymbolAddress((void**)&sp3, g_sp3);
    cudaGetSymbolAddress((void**)&colsum, g_colsum);
    cudaGetSymbolAddress((void**)&attn0, g_attn0);
    cudaGetSymbolAddress((void**)&attn1, g_attn1);
    cudaGetSymbolAddress((void**)&zb, g_zb);
    cudaGetSymbolAddress((void**)&rp_w, g_rp_w);
    cudaGetSymbolAddress((void**)&rp_wb, g_rp_wb);
    cudaGetSymbolAddress((void**)&rp_c, g_rp_c);
    cudaGetSymbolAddress((void**)&src_w, g_src_w);
    cudaGetSymbolAddress((void**)&src_wb, g_src_wb);
    cudaGetSymbolAddress((void**)&src_c, g_src_c);
    cudaGetSymbolAddress((void**)&cnt, g_cnt);
    cudaGetSymbolAddress((void**)&aux, g_aux);

    int* cnt_w  = cnt;
    int* cnt_wb = cnt + NP;
    int* cnt_c  = cnt + NP + NA;
    int* aux_w  = aux;
    int* aux_wb = aux + 256;
    int* aux_c  = aux + 512;

    const int EB = (EE + 255) / 256;
    const int BW  = (NP + 255) / 256;
    const int BWB = (NA + 255) / 256;

    // ---- CSR build phase A (histogram + scans); paper GEMM hoisted to slot ~6 so
    //      the ncu capture (-s 5 -c 1) finally profiles the heavy tf32 kernel ----
    cudaMemsetAsync(cnt, 0, (2 * NP + NA) * sizeof(int));
    {
        H3 h; h.dst[0] = ei_w + EE; h.dst[1] = ei_wb + EE; h.dst[2] = ei_c + EE;
        h.cnt[0] = cnt_w; h.cnt[1] = cnt_wb; h.cnt[2] = cnt_c;
        hist3_k<<<dim3(EB, 3), 256>>>(h);
    }
    {
        SC3 s;
        s.cnt[0] = cnt_w;  s.rowptr[0] = rp_w;  s.aux[0] = aux_w;  s.n[0] = NP;
        s.cnt[1] = cnt_wb; s.rowptr[1] = rp_wb; s.aux[1] = aux_wb; s.n[1] = NA;
        s.cnt[2] = cnt_c;  s.rowptr[2] = rp_c;  s.aux[2] = aux_c;  s.n[2] = NP;
        scan_blk3_k<<<dim3(BW, 3), 256>>>(s);
    }
    {
        SA3 s;
        s.aux[0] = aux_w; s.nb[0] = BW;
        s.aux[1] = aux_wb; s.nb[1] = BWB;
        s.aux[2] = aux_c; s.nb[2] = BW;
        scan_aux3_k<<<3, 256>>>(s);
    }
    {
        AD3 s;
        s.rowptr[0] = rp_w;  s.aux[0] = aux_w;  s.n[0] = NP;
        s.rowptr[1] = rp_wb; s.aux[1] = aux_wb; s.n[1] = NA;
        s.rowptr[2] = rp_c;  s.aux[2] = aux_c;  s.n[2] = NP;
        scan_add3_k<<<dim3(BW, 3), 256>>>(s);
    }

    // layer-0 paper projection (independent of CSR) — profiling target
    sgemm_k<0, 0, 0><<<(NP + 127) / 128, 256>>>(
        x_paper, nullptr, nullptr, proj_w + (size_t)128 * 128, proj_b + 128,
        xp, nullptr, NP, 128);

    // ---- CSR build phase B (scatter) ----
    cudaMemsetAsync(cnt, 0, (2 * NP + NA) * sizeof(int));
    {
        S3 s;
        s.ei[0] = ei_w;  s.rowptr[0] = rp_w;  s.cursor[0] = cnt_w;  s.srcs[0] = src_w;
        s.ei[1] = ei_wb; s.rowptr[1] = rp_wb; s.cursor[1] = cnt_wb; s.srcs[1] = src_wb;
        s.ei[2] = ei_c;  s.rowptr[2] = rp_c;  s.cursor[2] = cnt_c;  s.srcs[2] = src_c;
        scatter3_k<<<dim3(EB, 3), 256>>>(s);
    }

    // ---- folded author projection: Wc = Wa @ W0a; xa = x_author @ Wc + b0a ----
    sgemm_k<0, 0, 0><<<1, 256>>>(
        Wa, nullptr, nullptr, proj_w, zb, Wc, nullptr, 64, 128);
    sgemm_k<0, 0, 0><<<(NA + 127) / 128, 256>>>(
        x_author, nullptr, nullptr, Wc, proj_b, xa, nullptr, NA, 64);

    // =============================== layer 0 ===============================
    {   // author scores: writes-src, written_by-dst
        MS ms; ms.nsc = 2;
        ms.att[0] = att_src + 0 * 128; ms.out[0] = sa0;
        ms.att[1] = att_dst + 1 * 128; ms.out[1] = sa1;
        ms.att[2] = ms.att[0]; ms.out[2] = sa0; ms.att[3] = ms.att[0]; ms.out[3] = sa0;
        att_multi_k<<<(NA * 8 + 255) / 256, 256>>>(xa, ms, NA);
    }
    {   // paper scores: writes-dst, wb-src, cites-src, cites-dst
        MS ms; ms.nsc = 4;
        ms.att[0] = att_dst + 0 * 128; ms.out[0] = sp0;
        ms.att[1] = att_src + 1 * 128; ms.out[1] = sp1;
        ms.att[2] = att_src + 2 * 128; ms.out[2] = sp2;
        ms.att[3] = att_dst + 2 * 128; ms.out[3] = sp3;
        att_multi_k<<<(NP * 8 + 255) / 256, 256>>>(xp, ms, NP);
    }

    {   // merged paper aggregations: writes + cites (WS ~73MB < L2)
        AG2 a;
        a.rowptr[0] = rp_w; a.srcs[0] = src_w; a.asrc[0] = sa0; a.adst[0] = sp0;
        a.xh[0] = xa; a.agg[0] = aggP0;
        a.rowptr[1] = rp_c; a.srcs[1] = src_c; a.asrc[1] = sp2; a.adst[1] = sp3;
        a.xh[1] = xp; a.agg[1] = aggP1;
        agg2_k<<<dim3((NP * 32 + 255) / 256, 2), 256>>>(a, NP);
    }
    agg_csr_k<<<(NA * 32 + 255) / 256, 256>>>(rp_wb, src_wb, sp1, sa1, xp, aggA, NA);

    cudaMemsetAsync(colsum, 0, 2 * 128 * sizeof(float));
    sgemm_k<1, 1, 0><<<dim3((NP + 127) / 128, 2), 256>>>(
        aggP0, aggP1, nullptr, klin_w, klin_b, nullptr, colsum, NP, 128);
    sem_attn_k<<<1, 128>>>(colsum, q, attn0);

    // =============================== layer 1 ===============================
    sgemm_k<0, 1, 0><<<(NA + 127) / 128, 256>>>(
        aggA, nullptr, nullptr, proj_w + (size_t)2 * 128 * 128, proj_b + 2 * 128,
        xa, nullptr, NA, 128);
    sgemm_k<0, 0, 1><<<(NP + 127) / 128, 256>>>(
        aggP0, aggP1, attn0, proj_w + (size_t)3 * 128 * 128, proj_b + 3 * 128,
        xp, nullptr, NP, 128);

    {   // author scores: writes-src
        MS ms; ms.nsc = 1;
        ms.att[0] = att_src + 3 * 128; ms.out[0] = sa0;
        ms.att[1] = ms.att[0]; ms.out[1] = sa0;
        ms.att[2] = ms.att[0]; ms.out[2] = sa0;
        ms.att[3] = ms.att[0]; ms.out[3] = sa0;
        att_multi_k<<<(NA * 8 + 255) / 256, 256>>>(xa, ms, NA);
    }
    {   // paper scores: writes-dst, cites-src, cites-dst
        MS ms; ms.nsc = 3;
        ms.att[0] = att_dst + 3 * 128; ms.out[0] = sp0;
        ms.att[1] = att_src + 5 * 128; ms.out[1] = sp2;
        ms.att[2] = att_dst + 5 * 128; ms.out[2] = sp3;
        ms.att[3] = ms.att[0]; ms.out[3] = sp0;
        att_multi_k<<<(NP * 8 + 255) / 256, 256>>>(xp, ms, NP);
    }

    {
        AG2 a;
        a.rowptr[0] = rp_w; a.srcs[0] = src_w; a.asrc[0] = sa0; a.adst[0] = sp0;
        a.xh[0] = xa; a.agg[0] = aggP0;
        a.rowptr[1] = rp_c; a.srcs[1] = src_c; a.asrc[1] = sp2; a.adst[1] = sp3;
        a.xh[1] = xp; a.agg[1] = aggP1;
        agg2_k<<<dim3((NP * 32 + 255) / 256, 2), 256>>>(a, NP);
    }

    cudaMemsetAsync(colsum, 0, 2 * 128 * sizeof(float));
    sgemm_k<1, 1, 0><<<dim3((NP + 127) / 128, 2), 256>>>(
        aggP0, aggP1, nullptr, klin_w + (size_t)128 * 128, klin_b + 128,
        nullptr, colsum, NP, 128);
    sem_attn_k<<<1, 128>>>(colsum, q + 128, attn1);

    final_lin_k<<<(NP + 255) / 256, 256>>>(aggP0, aggP1, attn1, lin_w, lin_b, out);
}

// round 14
// speedup vs baseline: 1.0719x; 1.0719x over previous
#include <cuda_runtime.h>
#include <cuda_fp16.h>
#include <cstddef>

#define NA 20000
#define NP 40000
#define EE 400000
#define HID 128
#define NCLS 16

// ----------------------------- scratch (static device globals) -------------------
__device__ float  g_auth0[NA * HID];        // x_author @ Wa  (fp32)
__device__ float  g_aggA[NA * HID];
__device__ __half g_xa[NA * HID];           // xh author  (fp16 storage)
__device__ __half g_xp[NP * HID];           // xh paper   (fp16 storage)
__device__ float  g_aggP0[NP * HID];
__device__ float  g_aggP1[NP * HID];
__device__ float  g_sa0[NA * 8];
__device__ float  g_sa1[NA * 8];
__device__ float  g_sp0[NP * 8];
__device__ float  g_sp1[NP * 8];
__device__ float  g_sp2[NP * 8];
__device__ float  g_sp3[NP * 8];
__device__ float  g_colsum[2 * HID];
__device__ float  g_attn0[2];
__device__ float  g_attn1[2];
__device__ float  g_zb[HID];
__device__ int g_rp_w[NP + 1];
__device__ int g_rp_wb[NA + 1];
__device__ int g_rp_c[NP + 1];
__device__ int g_src_w[EE];
__device__ int g_src_wb[EE];
__device__ int g_src_c[EE];
__device__ int g_cnt[NP + NA + NP];
__device__ int g_aux[3 * 256];

// ----------------------------- CSR build (R11-proven) -----------------------------
struct H3 { const int* dst[3]; int* cnt[3]; };
__global__ void hist3_k(H3 p)
{
    const int y = blockIdx.y;
    const int e = blockIdx.x * blockDim.x + threadIdx.x;
    if (e < EE) atomicAdd(&p.cnt[y][__ldg(&p.dst[y][e])], 1);
}

struct SC3 { const int* cnt[3]; int* rowptr[3]; int* aux[3]; int n[3]; };
__global__ void scan_blk3_k(SC3 p)
{
    const int y = blockIdx.y;
    const int n = p.n[y];
    if (blockIdx.x * 256 >= n) return;
    __shared__ int s[256];
    const int tid = threadIdx.x;
    const int i = blockIdx.x * 256 + tid;
    s[tid] = (i < n) ? p.cnt[y][i] : 0;
    __syncthreads();
#pragma unroll
    for (int off = 1; off < 256; off <<= 1) {
        int t = (tid >= off) ? s[tid - off] : 0;
        __syncthreads();
        s[tid] += t;
        __syncthreads();
    }
    if (i < n) p.rowptr[y][i + 1] = s[tid];
    if (tid == 255) p.aux[y][blockIdx.x] = s[255];
}

struct SA3 { int* aux[3]; int nb[3]; };
__global__ void scan_aux3_k(SA3 p)
{
    const int y = blockIdx.x;
    const int nb = p.nb[y];
    __shared__ int s[256];
    const int tid = threadIdx.x;
    int v = (tid < nb) ? p.aux[y][tid] : 0;
    s[tid] = v;
    __syncthreads();
#pragma unroll
    for (int off = 1; off < 256; off <<= 1) {
        int t = (tid >= off) ? s[tid - off] : 0;
        __syncthreads();
        s[tid] += t;
        __syncthreads();
    }
    if (tid < nb) p.aux[y][tid] = s[tid] - v;
}

struct AD3 { int* rowptr[3]; const int* aux[3]; int n[3]; };
__global__ void scan_add3_k(AD3 p)
{
    const int y = blockIdx.y;
    const int i = blockIdx.x * blockDim.x + threadIdx.x;
    if (i < p.n[y]) p.rowptr[y][i + 1] += p.aux[y][i >> 8];
    if (i == 0) p.rowptr[y][0] = 0;
}

struct S3 { const int* ei[3]; const int* rowptr[3]; int* cursor[3]; int* srcs[3]; };
__global__ void scatter3_k(S3 p)
{
    const int y = blockIdx.y;
    const int e = blockIdx.x * blockDim.x + threadIdx.x;
    if (e >= EE) return;
    const int si = __ldg(&p.ei[y][e]);
    const int di = __ldg(&p.ei[y][EE + e]);
    const int pos = atomicAdd(&p.cursor[y][di], 1);
    p.srcs[y][p.rowptr[y][di] + pos] = si;
}

// ----------------------------- fused CSR aggregation (fp16 xh gather) --------------
// One warp per dst node; lane-parallel index load + shfl broadcast (R11-proven).
// xh stored fp16: lane covers 4 features = one uint2 (8B) -> half the gather bytes.
__global__ __launch_bounds__(256)
void agg_csr_k(const int* __restrict__ rowptr, const int* __restrict__ srcs,
               const float* __restrict__ asrc, const float* __restrict__ adst,
               const __half* __restrict__ xh, float* __restrict__ agg, int ndst)
{
    const int w = (blockIdx.x * blockDim.x + threadIdx.x) >> 5;
    if (w >= ndst) return;
    const int lane = threadIdx.x & 31;
    const int h = lane >> 2;
    const int start = __ldg(&rowptr[w]);
    const int end   = __ldg(&rowptr[w + 1]);
    const float ad = __ldg(&adst[(size_t)w * 8 + h]);
    const uint2* __restrict__ xh2 = (const uint2*)xh;   // 32 uint2 per 128-half row

    float4 acc = make_float4(0.f, 0.f, 0.f, 0.f);
    float den = 0.f;
    for (int p0 = start; p0 < end; p0 += 32) {
        const int nedge = min(32, end - p0);
        const int myidx = (lane < nedge) ? __ldg(&srcs[p0 + lane]) : 0;
#pragma unroll 4
        for (int j = 0; j < nedge; j++) {
            const int si = __shfl_sync(0xffffffffu, myidx, j);
            float a = __ldg(&asrc[(size_t)si * 8 + h]) + ad;
            a = (a >= 0.f) ? a : 0.2f * a;
            const float e = __expf(a);
            den += e;
            uint2 u = __ldg(&xh2[(size_t)si * 32 + lane]);
            float2 fa = __half22float2(*(const __half2*)&u.x);
            float2 fb = __half22float2(*(const __half2*)&u.y);
            acc.x = fmaf(e, fa.x, acc.x);
            acc.y = fmaf(e, fa.y, acc.y);
            acc.z = fmaf(e, fb.x, acc.z);
            acc.w = fmaf(e, fb.y, acc.w);
        }
    }
    const float inv = 1.f / (den + 1e-16f);
    acc.x *= inv; acc.y *= inv; acc.z *= inv; acc.w *= inv;
    ((float4*)agg)[(size_t)w * 32 + lane] = acc;
}

// ----------------------------- tf32 mma helpers ------------------------------------
__device__ __forceinline__ unsigned f2tf(float f) {
    unsigned u;
    asm("cvt.rna.tf32.f32 %0, %1;" : "=r"(u) : "f"(f));
    return u;
}
__device__ __forceinline__ float tfbits(float f) {
    return __uint_as_float(f2tf(f));
}
__device__ __forceinline__ void mma_tf32(float4& d, const unsigned* a,
                                         unsigned b0, unsigned b1) {
    asm volatile(
        "mma.sync.aligned.m16n8k8.row.col.f32.tf32.tf32.f32 "
        "{%0,%1,%2,%3}, {%4,%5,%6,%7}, {%8,%9}, {%0,%1,%2,%3};"
        : "+f"(d.x), "+f"(d.y), "+f"(d.z), "+f"(d.w)
        : "r"(a[0]), "r"(a[1]), "r"(a[2]), "r"(a[3]), "r"(b0), "r"(b1));
}

// ----------------------------- GEMM (tf32, k-tile 16; R11-proven) ------------------
// OUTH=1: store C as fp16 (half2 pairs) — used for xh-producing projections.
template <int TANH, int RELUA, int COMBINE, int OUTH>
__global__ __launch_bounds__(256)
void sgemm_k(const float* __restrict__ A0, const float* __restrict__ A1,
             const float* __restrict__ attnp,
             const float* __restrict__ B, const float* __restrict__ bias,
             void* __restrict__ Cv, float* __restrict__ colsum, int M, int K)
{
    __shared__ alignas(16) float As[16][136];
    __shared__ alignas(16) float Bs[16][136];

    const float* A = (TANH && blockIdx.y) ? A1 : A0;
    float* cs = TANH ? colsum + blockIdx.y * 128 : colsum;

    const int tid = threadIdx.x;
    const int lane = tid & 31;
    const int warp = tid >> 5;
    const int wm = warp & 3;
    const int wn = warp >> 2;
    const int g = lane >> 2;
    const int t = lane & 3;
    const int block_row = blockIdx.x * 128;

    const int a_row = tid >> 1;
    const int a_col = (tid & 1) * 8;
    const int b_row = tid >> 4;
    const int b_col = (tid & 15) * 8;

    float ca0 = 0.f, ca1 = 0.f;
    if constexpr (COMBINE) { ca0 = __ldg(&attnp[0]); ca1 = __ldg(&attnp[1]); }

    const int gr = block_row + a_row;
    const bool arow_ok = (gr < M);

    float4 d[2][8];
#pragma unroll
    for (int i = 0; i < 2; i++)
#pragma unroll
        for (int j = 0; j < 8; j++) d[i][j] = make_float4(0.f, 0.f, 0.f, 0.f);

    float4 av0, av1, bv0, bv1;

    auto loadA = [&](int k0, float4& o0, float4& o1) {
        o0 = make_float4(0.f, 0.f, 0.f, 0.f);
        o1 = o0;
        if (arow_ok) {
            o0 = *(const float4*)(A + (size_t)gr * K + k0 + a_col);
            o1 = *(const float4*)(A + (size_t)gr * K + k0 + a_col + 4);
            if constexpr (COMBINE) {
                float4 w0 = *(const float4*)(A1 + (size_t)gr * K + k0 + a_col);
                float4 w1 = *(const float4*)(A1 + (size_t)gr * K + k0 + a_col + 4);
                o0.x = ca0 * fmaxf(o0.x, 0.f) + ca1 * fmaxf(w0.x, 0.f);
                o0.y = ca0 * fmaxf(o0.y, 0.f) + ca1 * fmaxf(w0.y, 0.f);
                o0.z = ca0 * fmaxf(o0.z, 0.f) + ca1 * fmaxf(w0.z, 0.f);
                o0.w = ca0 * fmaxf(o0.w, 0.f) + ca1 * fmaxf(w0.w, 0.f);
                o1.x = ca0 * fmaxf(o1.x, 0.f) + ca1 * fmaxf(w1.x, 0.f);
                o1.y = ca0 * fmaxf(o1.y, 0.f) + ca1 * fmaxf(w1.y, 0.f);
                o1.z = ca0 * fmaxf(o1.z, 0.f) + ca1 * fmaxf(w1.z, 0.f);
                o1.w = ca0 * fmaxf(o1.w, 0.f) + ca1 * fmaxf(w1.w, 0.f);
            } else if constexpr (RELUA || TANH) {
                o0.x = fmaxf(o0.x, 0.f); o0.y = fmaxf(o0.y, 0.f);
                o0.z = fmaxf(o0.z, 0.f); o0.w = fmaxf(o0.w, 0.f);
                o1.x = fmaxf(o1.x, 0.f); o1.y = fmaxf(o1.y, 0.f);
                o1.z = fmaxf(o1.z, 0.f); o1.w = fmaxf(o1.w, 0.f);
            }
        }
    };

    loadA(0, av0, av1);
    bv0 = *(const float4*)(B + (size_t)b_row * 128 + b_col);
    bv1 = *(const float4*)(B + (size_t)b_row * 128 + b_col + 4);

    for (int k0 = 0; k0 < K; k0 += 16) {
        As[a_col + 0][a_row] = tfbits(av0.x);
        As[a_col + 1][a_row] = tfbits(av0.y);
        As[a_col + 2][a_row] = tfbits(av0.z);
        As[a_col + 3][a_row] = tfbits(av0.w);
        As[a_col + 4][a_row] = tfbits(av1.x);
        As[a_col + 5][a_row] = tfbits(av1.y);
        As[a_col + 6][a_row] = tfbits(av1.z);
        As[a_col + 7][a_row] = tfbits(av1.w);
        Bs[b_row][b_col + 0] = tfbits(bv0.x);
        Bs[b_row][b_col + 1] = tfbits(bv0.y);
        Bs[b_row][b_col + 2] = tfbits(bv0.z);
        Bs[b_row][b_col + 3] = tfbits(bv0.w);
        Bs[b_row][b_col + 4] = tfbits(bv1.x);
        Bs[b_row][b_col + 5] = tfbits(bv1.y);
        Bs[b_row][b_col + 6] = tfbits(bv1.z);
        Bs[b_row][b_col + 7] = tfbits(bv1.w);
        __syncthreads();

        if (k0 + 16 < K) {
            loadA(k0 + 16, av0, av1);
            bv0 = *(const float4*)(B + (size_t)(k0 + 16 + b_row) * 128 + b_col);
            bv1 = *(const float4*)(B + (size_t)(k0 + 16 + b_row) * 128 + b_col + 4);
        }

#pragma unroll
        for (int kk = 0; kk < 16; kk += 8) {
            unsigned au[2][4];
#pragma unroll
            for (int mi = 0; mi < 2; mi++) {
                const int rb = wm * 32 + mi * 16 + g;
                au[mi][0] = __float_as_uint(As[kk + t][rb]);
                au[mi][1] = __float_as_uint(As[kk + t][rb + 8]);
                au[mi][2] = __float_as_uint(As[kk + t + 4][rb]);
                au[mi][3] = __float_as_uint(As[kk + t + 4][rb + 8]);
            }
#pragma unroll
            for (int ni = 0; ni < 8; ni++) {
                const int nb = wn * 64 + ni * 8 + g;
                const unsigned b0 = __float_as_uint(Bs[kk + t][nb]);
                const unsigned b1 = __float_as_uint(Bs[kk + t + 4][nb]);
                mma_tf32(d[0][ni], au[0], b0, b1);
                mma_tf32(d[1][ni], au[1], b0, b1);
            }
        }
        __syncthreads();
    }

    float2 bb[8];
#pragma unroll
    for (int ni = 0; ni < 8; ni++) {
        const int c = wn * 64 + ni * 8 + t * 2;
        bb[ni] = make_float2(__ldg(&bias[c]), __ldg(&bias[c + 1]));
    }

    if constexpr (TANH) {
        __shared__ float red[128];
        if (tid < 128) red[tid] = 0.f;
        __syncthreads();
#pragma unroll
        for (int ni = 0; ni < 8; ni++) {
            const int c = wn * 64 + ni * 8 + t * 2;
            float sx = 0.f, sy = 0.f;
#pragma unroll
            for (int mi = 0; mi < 2; mi++) {
                const int r0 = block_row + wm * 32 + mi * 16 + g;
                const int r1 = r0 + 8;
                if (r0 < M) {
                    sx += tanhf(d[mi][ni].x + bb[ni].x);
                    sy += tanhf(d[mi][ni].y + bb[ni].y);
                }
                if (r1 < M) {
                    sx += tanhf(d[mi][ni].z + bb[ni].x);
                    sy += tanhf(d[mi][ni].w + bb[ni].y);
                }
            }
            atomicAdd(&red[c], sx);
            atomicAdd(&red[c + 1], sy);
        }
        __syncthreads();
        if (tid < 128) atomicAdd(&cs[tid], red[tid]);
    } else if constexpr (OUTH) {
        __half* C = (__half*)Cv;
#pragma unroll
        for (int mi = 0; mi < 2; mi++) {
            const int r0 = block_row + wm * 32 + mi * 16 + g;
            const int r1 = r0 + 8;
#pragma unroll
            for (int ni = 0; ni < 8; ni++) {
                const int c = wn * 64 + ni * 8 + t * 2;
                if (r0 < M)
                    *(__half2*)(C + (size_t)r0 * 128 + c) =
                        __floats2half2_rn(d[mi][ni].x + bb[ni].x, d[mi][ni].y + bb[ni].y);
                if (r1 < M)
                    *(__half2*)(C + (size_t)r1 * 128 + c) =
                        __floats2half2_rn(d[mi][ni].z + bb[ni].x, d[mi][ni].w + bb[ni].y);
            }
        }
    } else {
        float* C = (float*)Cv;
#pragma unroll
        for (int mi = 0; mi < 2; mi++) {
            const int r0 = block_row + wm * 32 + mi * 16 + g;
            const int r1 = r0 + 8;
#pragma unroll
            for (int ni = 0; ni < 8; ni++) {
                const int c = wn * 64 + ni * 8 + t * 2;
                if (r0 < M)
                    *(float2*)(C + (size_t)r0 * 128 + c) =
                        make_float2(d[mi][ni].x + bb[ni].x, d[mi][ni].y + bb[ni].y);
                if (r1 < M)
                    *(float2*)(C + (size_t)r1 * 128 + c) =
                        make_float2(d[mi][ni].z + bb[ni].x, d[mi][ni].w + bb[ni].y);
            }
        }
    }
}

// ----------------------------- multi attention scores (fp16 xh) --------------------
struct MS { const float* att[4]; float* out[4]; int nsc; };

__global__ void att_multi_k(const __half* __restrict__ xh, MS ms, int N)
{
    const int t = blockIdx.x * blockDim.x + threadIdx.x;
    if (t >= N * 8) return;
    const int n = t >> 3, h = t & 7;
    // head h features = 16 halfs = 32B = two uint4 loads
    const uint4* xr = (const uint4*)(xh + (size_t)n * HID + h * 16);
    uint4 u0 = __ldg(&xr[0]);
    uint4 u1 = __ldg(&xr[1]);
    float xf[16];
    {
        const unsigned* uw = &u0.x;
#pragma unroll
        for (int i = 0; i < 4; i++) {
            float2 f = __half22float2(*(const __half2*)&uw[i]);
            xf[i * 2] = f.x; xf[i * 2 + 1] = f.y;
        }
        const unsigned* vw = &u1.x;
#pragma unroll
        for (int i = 0; i < 4; i++) {
            float2 f = __half22float2(*(const __half2*)&vw[i]);
            xf[8 + i * 2] = f.x; xf[8 + i * 2 + 1] = f.y;
        }
    }
#pragma unroll
    for (int s = 0; s < 4; s++) {
        if (s < ms.nsc) {
            const float4* ar = (const float4*)(ms.att[s] + h * 16);
            float r = 0.f;
#pragma unroll
            for (int i = 0; i < 4; i++) {
                float4 a = __ldg(&ar[i]);
                r += xf[i * 4] * a.x + xf[i * 4 + 1] * a.y
                   + xf[i * 4 + 2] * a.z + xf[i * 4 + 3] * a.w;
            }
            ms.out[s][t] = r;
        }
    }
}

// ----------------------------- semantic attention weights (M=2) --------------------
__global__ void sem_attn_k(const float* __restrict__ colsum, const float* __restrict__ q,
                           float* __restrict__ attn)
{
    __shared__ float r0[128], r1[128];
    const int t = threadIdx.x;
    const float qv = q[t];
    r0[t] = qv * colsum[t];
    r1[t] = qv * colsum[128 + t];
    __syncthreads();
    for (int s = 64; s > 0; s >>= 1) {
        if (t < s) { r0[t] += r0[t + s]; r1[t] += r1[t + s]; }
        __syncthreads();
    }
    if (t == 0) {
        const float s0 = r0[0] / (float)NP;
        const float s1 = r1[0] / (float)NP;
        const float m = fmaxf(s0, s1);
        const float e0 = __expf(s0 - m), e1 = __expf(s1 - m);
        const float inv = 1.f / (e0 + e1);
        attn[0] = e0 * inv;
        attn[1] = e1 * inv;
    }
}

// ----------------------------- final linear (fused layer-1 combine + relu) ---------
__global__ __launch_bounds__(256)
void final_lin_k(const float* __restrict__ s0, const float* __restrict__ s1,
                 const float* __restrict__ attn, const float* __restrict__ W,
                 const float* __restrict__ b, float* __restrict__ out)
{
    __shared__ float Ws[128 * NCLS];
    for (int i = threadIdx.x; i < 128 * NCLS; i += blockDim.x) Ws[i] = W[i];
    __syncthreads();
    const int n = blockIdx.x * blockDim.x + threadIdx.x;
    if (n >= NP) return;
    const float a0 = __ldg(&attn[0]);
    const float a1 = __ldg(&attn[1]);
    float acc[NCLS];
#pragma unroll
    for (int c = 0; c < NCLS; c++) acc[c] = __ldg(&b[c]);
    const float4* x0 = (const float4*)(s0 + (size_t)n * 128);
    const float4* x1 = (const float4*)(s1 + (size_t)n * 128);
#pragma unroll
    for (int k4 = 0; k4 < 32; k4++) {
        float4 u = __ldg(&x0[k4]);
        float4 v = __ldg(&x1[k4]);
        const float xs[4] = {
            a0 * fmaxf(u.x, 0.f) + a1 * fmaxf(v.x, 0.f),
            a0 * fmaxf(u.y, 0.f) + a1 * fmaxf(v.y, 0.f),
            a0 * fmaxf(u.z, 0.f) + a1 * fmaxf(v.z, 0.f),
            a0 * fmaxf(u.w, 0.f) + a1 * fmaxf(v.w, 0.f)};
#pragma unroll
        for (int uu = 0; uu < 4; uu++) {
            const int k = k4 * 4 + uu;
#pragma unroll
            for (int c = 0; c < NCLS; c++)
                acc[c] = fmaf(xs[uu], Ws[k * NCLS + c], acc[c]);
        }
    }
    float4* op = (float4*)(out + (size_t)n * NCLS);
#pragma unroll
    for (int c4 = 0; c4 < 4; c4++)
        op[c4] = make_float4(acc[c4 * 4], acc[c4 * 4 + 1], acc[c4 * 4 + 2], acc[c4 * 4 + 3]);
}

// ----------------------------- host orchestration ----------------------------------
extern "C" void kernel_launch(void* const* d_in, const int* in_sizes, int n_in,
                              void* d_out, int out_size)
{
    const float* x_author = (const float*)d_in[0];
    const float* x_paper  = (const float*)d_in[1];
    const float* Wa       = (const float*)d_in[2];
    const float* proj_w   = (const float*)d_in[3];
    const float* proj_b   = (const float*)d_in[4];
    const float* att_src  = (const float*)d_in[5];
    const float* att_dst  = (const float*)d_in[6];
    const float* klin_w   = (const float*)d_in[7];
    const float* klin_b   = (const float*)d_in[8];
    const float* q        = (const float*)d_in[9];
    const float* lin_w    = (const float*)d_in[10];
    const float* lin_b    = (const float*)d_in[11];
    const int*   ei_w     = (const int*)d_in[12];
    const int*   ei_wb    = (const int*)d_in[13];
    const int*   ei_c     = (const int*)d_in[14];
    float* out = (float*)d_out;

    float *auth0, *aggA, *aggP0, *aggP1;
    __half *xa, *xp;
    float *sa0, *sa1, *sp0, *sp1, *sp2, *sp3, *colsum, *attn0, *attn1, *zb;
    int *rp_w, *rp_wb, *rp_c, *src_w, *src_wb, *src_c, *cnt, *aux;
    cudaGetSymbolAddress((void**)&auth0, g_auth0);
    cudaGetSymbolAddress((void**)&aggA, g_aggA);
    cudaGetSymbolAddress((void**)&xa, g_xa);
    cudaGetSymbolAddress((void**)&xp, g_xp);
    cudaGetSymbolAddress((void**)&aggP0, g_aggP0);
    cudaGetSymbolAddress((void**)&aggP1, g_aggP1);
    cudaGetSymbolAddress((void**)&sa0, g_sa0);
    cudaGetSymbolAddress((void**)&sa1, g_sa1);
    cudaGetSymbolAddress((void**)&sp0, g_sp0);
    cudaGetSymbolAddress((void**)&sp1, g_sp1);
    cudaGetSymbolAddress((void**)&sp2, g_sp2);
    cudaGetSymbolAddress((void**)&sp3, g_sp3);
    cudaGetSymbolAddress((void**)&colsum, g_colsum);
    cudaGetSymbolAddress((void**)&attn0, g_attn0);
    cudaGetSymbolAddress((void**)&attn1, g_attn1);
    cudaGetSymbolAddress((void**)&zb, g_zb);
    cudaGetSymbolAddress((void**)&rp_w, g_rp_w);
    cudaGetSymbolAddress((void**)&rp_wb, g_rp_wb);
    cudaGetSymbolAddress((void**)&rp_c, g_rp_c);
    cudaGetSymbolAddress((void**)&src_w, g_src_w);
    cudaGetSymbolAddress((void**)&src_wb, g_src_wb);
    cudaGetSymbolAddress((void**)&src_c, g_src_c);
    cudaGetSymbolAddress((void**)&cnt, g_cnt);
    cudaGetSymbolAddress((void**)&aux, g_aux);

    int* cnt_w  = cnt;
    int* cnt_wb = cnt + NP;
    int* cnt_c  = cnt + NP + NA;
    int* aux_w  = aux;
    int* aux_wb = aux + 256;
    int* aux_c  = aux + 512;

    const int EB = (EE + 255) / 256;
    const int BW  = (NP + 255) / 256;
    const int BWB = (NA + 255) / 256;

    // ---- CSR build (merged across edge types; R11 order) ----
    cudaMemsetAsync(cnt, 0, (2 * NP + NA) * sizeof(int));
    {
        H3 h; h.dst[0] = ei_w + EE; h.dst[1] = ei_wb + EE; h.dst[2] = ei_c + EE;
        h.cnt[0] = cnt_w; h.cnt[1] = cnt_wb; h.cnt[2] = cnt_c;
        hist3_k<<<dim3(EB, 3), 256>>>(h);
    }
    {
        SC3 s;
        s.cnt[0] = cnt_w;  s.rowptr[0] = rp_w;  s.aux[0] = aux_w;  s.n[0] = NP;
        s.cnt[1] = cnt_wb; s.rowptr[1] = rp_wb; s.aux[1] = aux_wb; s.n[1] = NA;
        s.cnt[2] = cnt_c;  s.rowptr[2] = rp_c;  s.aux[2] = aux_c;  s.n[2] = NP;
        scan_blk3_k<<<dim3(BW, 3), 256>>>(s);
    }
    {
        SA3 s;
        s.aux[0] = aux_w; s.nb[0] = BW;
        s.aux[1] = aux_wb; s.nb[1] = BWB;
        s.aux[2] = aux_c; s.nb[2] = BW;
        scan_aux3_k<<<3, 256>>>(s);
    }
    {
        AD3 s;
        s.rowptr[0] = rp_w;  s.aux[0] = aux_w;  s.n[0] = NP;
        s.rowptr[1] = rp_wb; s.aux[1] = aux_wb; s.n[1] = NA;
        s.rowptr[2] = rp_c;  s.aux[2] = aux_c;  s.n[2] = NP;
        scan_add3_k<<<dim3(BW, 3), 256>>>(s);
    }
    cudaMemsetAsync(cnt, 0, (2 * NP + NA) * sizeof(int));
    {
        S3 s;
        s.ei[0] = ei_w;  s.rowptr[0] = rp_w;  s.cursor[0] = cnt_w;  s.srcs[0] = src_w;
        s.ei[1] = ei_wb; s.rowptr[1] = rp_wb; s.cursor[1] = cnt_wb; s.srcs[1] = src_wb;
        s.ei[2] = ei_c;  s.rowptr[2] = rp_c;  s.cursor[2] = cnt_c;  s.srcs[2] = src_c;
        scatter3_k<<<dim3(EB, 3), 256>>>(s);
    }

    // author raw projection: [20000,64] @ [64,128] (no bias, fp32 out)
    sgemm_k<0, 0, 0, 0><<<(NA + 127) / 128, 256>>>(
        x_author, nullptr, nullptr, Wa, zb, auth0, nullptr, NA, 64);

    // =============================== layer 0 ===============================
    sgemm_k<0, 0, 0, 1><<<(NA + 127) / 128, 256>>>(
        auth0, nullptr, nullptr, proj_w, proj_b, xa, nullptr, NA, 128);
    sgemm_k<0, 0, 0, 1><<<(NP + 127) / 128, 256>>>(
        x_paper, nullptr, nullptr, proj_w + (size_t)128 * 128, proj_b + 128,
        xp, nullptr, NP, 128);

    {   // author scores: writes-src, written_by-dst
        MS ms; ms.nsc = 2;
        ms.att[0] = att_src + 0 * 128; ms.out[0] = sa0;
        ms.att[1] = att_dst + 1 * 128; ms.out[1] = sa1;
        ms.att[2] = ms.att[0]; ms.out[2] = sa0; ms.att[3] = ms.att[0]; ms.out[3] = sa0;
        att_multi_k<<<(NA * 8 + 255) / 256, 256>>>(xa, ms, NA);
    }
    {   // paper scores: writes-dst, wb-src, cites-src, cites-dst
        MS ms; ms.nsc = 4;
        ms.att[0] = att_dst + 0 * 128; ms.out[0] = sp0;
        ms.att[1] = att_src + 1 * 128; ms.out[1] = sp1;
        ms.att[2] = att_src + 2 * 128; ms.out[2] = sp2;
        ms.att[3] = att_dst + 2 * 128; ms.out[3] = sp3;
        att_multi_k<<<(NP * 8 + 255) / 256, 256>>>(xp, ms, NP);
    }

    // SEQUENTIAL aggregations (L2-resident working sets; R11-proven)
    agg_csr_k<<<(NP * 32 + 255) / 256, 256>>>(rp_w,  src_w,  sa0, sp0, xa, aggP0, NP);
    agg_csr_k<<<(NA * 32 + 255) / 256, 256>>>(rp_wb, src_wb, sp1, sa1, xp, aggA,  NA);
    agg_csr_k<<<(NP * 32 + 255) / 256, 256>>>(rp_c,  src_c,  sp2, sp3, xp, aggP1, NP);

    cudaMemsetAsync(colsum, 0, 2 * 128 * sizeof(float));
    sgemm_k<1, 1, 0, 0><<<dim3((NP + 127) / 128, 2), 256>>>(
        aggP0, aggP1, nullptr, klin_w, klin_b, nullptr, colsum, NP, 128);
    sem_attn_k<<<1, 128>>>(colsum, q, attn0);

    // =============================== layer 1 ===============================
    sgemm_k<0, 1, 0, 1><<<(NA + 127) / 128, 256>>>(
        aggA, nullptr, nullptr, proj_w + (size_t)2 * 128 * 128, proj_b + 2 * 128,
        xa, nullptr, NA, 128);
    sgemm_k<0, 0, 1, 1><<<(NP + 127) / 128, 256>>>(
        aggP0, aggP1, attn0, proj_w + (size_t)3 * 128 * 128, proj_b + 3 * 128,
        xp, nullptr, NP, 128);

    {   // author scores: writes-src
        MS ms; ms.nsc = 1;
        ms.att[0] = att_src + 3 * 128; ms.out[0] = sa0;
        ms.att[1] = ms.att[0]; ms.out[1] = sa0;
        ms.att[2] = ms.att[0]; ms.out[2] = sa0;
        ms.att[3] = ms.att[0]; ms.out[3] = sa0;
        att_multi_k<<<(NA * 8 + 255) / 256, 256>>>(xa, ms, NA);
    }
    {   // paper scores: writes-dst, cites-src, cites-dst
        MS ms; ms.nsc = 3;
        ms.att[0] = att_dst + 3 * 128; ms.out[0] = sp0;
        ms.att[1] = att_src + 5 * 128; ms.out[1] = sp2;
        ms.att[2] = att_dst + 5 * 128; ms.out[2] = sp3;
        ms.att[3] = ms.att[0]; ms.out[3] = sp0;
        att_multi_k<<<(NP * 8 + 255) / 256, 256>>>(xp, ms, NP);
    }

    agg_csr_k<<<(NP * 32 + 255) / 256, 256>>>(rp_w, src_w, sa0, sp0, xa, aggP0, NP);
    agg_csr_k<<<(NP * 32 + 255) / 256, 256>>>(rp_c, src_c, sp2, sp3, xp, aggP1, NP);

    cudaMemsetAsync(colsum, 0, 2 * 128 * sizeof(float));
    sgemm_k<1, 1, 0, 0><<<dim3((NP + 127) / 128, 2), 256>>>(
        aggP0, aggP1, nullptr, klin_w + (size_t)128 * 128, klin_b + 128,
        nullptr, colsum, NP, 128);
    sem_attn_k<<<1, 128>>>(colsum, q + 128, attn1);

    final_lin_k<<<(NP + 255) / 256, 256>>>(aggP0, aggP1, attn1, lin_w, lin_b, out);
}

// round 17
// speedup vs baseline: 1.0974x; 1.0238x over previous
#include <cuda_runtime.h>
#include <cuda_fp16.h>
#include <cstddef>

#define NA 20000
#define NP 40000
#define EE 400000
#define HID 128
#define NCLS 16

// ----------------------------- scratch (static device globals) -------------------
__device__ float  g_auth0[NA * HID];        // x_author @ Wa  (fp32)
__device__ float  g_aggA[NA * HID];
__device__ __half g_xa[NA * HID];           // xh author  (fp16 storage)
__device__ __half g_xp[NP * HID];           // xh paper   (fp16 storage)
__device__ float  g_aggP0[NP * HID];
__device__ float  g_aggP1[NP * HID];
__device__ float  g_sa0[NA * 8];
__device__ float  g_sa1[NA * 8];
__device__ float  g_sp0[NP * 8];
__device__ float  g_sp1[NP * 8];
__device__ float  g_sp2[NP * 8];
__device__ float  g_sp3[NP * 8];
__device__ float  g_colsum[2 * HID];        // zero-init; tanh kernel read-and-resets
__device__ float  g_attn0[2];
__device__ float  g_attn1[2];
__device__ float  g_zb[HID];
__device__ int    g_ticket;                 // zero-init; tanh kernel self-resets
__device__ int g_rp_w[NP + 1];
__device__ int g_rp_wb[NA + 1];
__device__ int g_rp_c[NP + 1];
__device__ int g_src_w[EE];
__device__ int g_src_wb[EE];
__device__ int g_src_c[EE];
__device__ int g_cnt[NP + NA + NP];
__device__ int g_aux[3 * 256];

// ----------------------------- CSR build (R11-proven) -----------------------------
struct H3 { const int* dst[3]; int* cnt[3]; };
__global__ void hist3_k(H3 p)
{
    const int y = blockIdx.y;
    const int e = blockIdx.x * blockDim.x + threadIdx.x;
    if (e < EE) atomicAdd(&p.cnt[y][__ldg(&p.dst[y][e])], 1);
}

struct SC3 { const int* cnt[3]; int* rowptr[3]; int* aux[3]; int n[3]; };
__global__ void scan_blk3_k(SC3 p)
{
    const int y = blockIdx.y;
    const int n = p.n[y];
    if (blockIdx.x * 256 >= n) return;
    __shared__ int s[256];
    const int tid = threadIdx.x;
    const int i = blockIdx.x * 256 + tid;
    s[tid] = (i < n) ? p.cnt[y][i] : 0;
    __syncthreads();
#pragma unroll
    for (int off = 1; off < 256; off <<= 1) {
        int t = (tid >= off) ? s[tid - off] : 0;
        __syncthreads();
        s[tid] += t;
        __syncthreads();
    }
    if (i < n) p.rowptr[y][i + 1] = s[tid];
    if (tid == 255) p.aux[y][blockIdx.x] = s[255];
}

struct SA3 { int* aux[3]; int nb[3]; };
__global__ void scan_aux3_k(SA3 p)
{
    const int y = blockIdx.x;
    const int nb = p.nb[y];
    __shared__ int s[256];
    const int tid = threadIdx.x;
    int v = (tid < nb) ? p.aux[y][tid] : 0;
    s[tid] = v;
    __syncthreads();
#pragma unroll
    for (int off = 1; off < 256; off <<= 1) {
        int t = (tid >= off) ? s[tid - off] : 0;
        __syncthreads();
        s[tid] += t;
        __syncthreads();
    }
    if (tid < nb) p.aux[y][tid] = s[tid] - v;
}

struct AD3 { int* rowptr[3]; const int* aux[3]; int n[3]; };
__global__ void scan_add3_k(AD3 p)
{
    const int y = blockIdx.y;
    const int i = blockIdx.x * blockDim.x + threadIdx.x;
    if (i < p.n[y]) p.rowptr[y][i + 1] += p.aux[y][i >> 8];
    if (i == 0) p.rowptr[y][0] = 0;
}

struct S3 { const int* ei[3]; const int* rowptr[3]; int* cursor[3]; int* srcs[3]; };
__global__ void scatter3_k(S3 p)
{
    const int y = blockIdx.y;
    const int e = blockIdx.x * blockDim.x + threadIdx.x;
    if (e >= EE) return;
    const int si = __ldg(&p.ei[y][e]);
    const int di = __ldg(&p.ei[y][EE + e]);
    const int pos = atomicAdd(&p.cursor[y][di], 1);
    p.srcs[y][p.rowptr[y][di] + pos] = si;
}

// ----------------------------- fused CSR aggregation (fp16 xh gather; R13) ---------
__global__ __launch_bounds__(256)
void agg_csr_k(const int* __restrict__ rowptr, const int* __restrict__ srcs,
               const float* __restrict__ asrc, const float* __restrict__ adst,
               const __half* __restrict__ xh, float* __restrict__ agg, int ndst)
{
    const int w = (blockIdx.x * blockDim.x + threadIdx.x) >> 5;
    if (w >= ndst) return;
    const int lane = threadIdx.x & 31;
    const int h = lane >> 2;
    const int start = __ldg(&rowptr[w]);
    const int end   = __ldg(&rowptr[w + 1]);
    const float ad = __ldg(&adst[(size_t)w * 8 + h]);
    const uint2* __restrict__ xh2 = (const uint2*)xh;

    float4 acc = make_float4(0.f, 0.f, 0.f, 0.f);
    float den = 0.f;
    for (int p0 = start; p0 < end; p0 += 32) {
        const int nedge = min(32, end - p0);
        const int myidx = (lane < nedge) ? __ldg(&srcs[p0 + lane]) : 0;
#pragma unroll 4
        for (int j = 0; j < nedge; j++) {
            const int si = __shfl_sync(0xffffffffu, myidx, j);
            float a = __ldg(&asrc[(size_t)si * 8 + h]) + ad;
            a = (a >= 0.f) ? a : 0.2f * a;
            const float e = __expf(a);
            den += e;
            uint2 u = __ldg(&xh2[(size_t)si * 32 + lane]);
            float2 fa = __half22float2(*(const __half2*)&u.x);
            float2 fb = __half22float2(*(const __half2*)&u.y);
            acc.x = fmaf(e, fa.x, acc.x);
            acc.y = fmaf(e, fa.y, acc.y);
            acc.z = fmaf(e, fb.x, acc.z);
            acc.w = fmaf(e, fb.y, acc.w);
        }
    }
    const float inv = 1.f / (den + 1e-16f);
    acc.x *= inv; acc.y *= inv; acc.z *= inv; acc.w *= inv;
    ((float4*)agg)[(size_t)w * 32 + lane] = acc;
}

// ----------------------------- tf32 mma helpers ------------------------------------
__device__ __forceinline__ unsigned f2tf(float f) {
    unsigned u;
    asm("cvt.rna.tf32.f32 %0, %1;" : "=r"(u) : "f"(f));
    return u;
}
__device__ __forceinline__ float tfbits(float f) {
    return __uint_as_float(f2tf(f));
}
__device__ __forceinline__ void mma_tf32(float4& d, const unsigned* a,
                                         unsigned b0, unsigned b1) {
    asm volatile(
        "mma.sync.aligned.m16n8k8.row.col.f32.tf32.tf32.f32 "
        "{%0,%1,%2,%3}, {%4,%5,%6,%7}, {%8,%9}, {%0,%1,%2,%3};"
        : "+f"(d.x), "+f"(d.y), "+f"(d.z), "+f"(d.w)
        : "r"(a[0]), "r"(a[1]), "r"(a[2]), "r"(a[3]), "r"(b0), "r"(b1));
}

// ----------------------------- GEMM (tf32) + fused epilogues -----------------------
// Non-TANH: optional attention-score epilogue (sc.nsc score sets computed from the
//           register-resident biased output; no xh re-read, no extra launch).
// TANH:     colsum accumulation + LAST-BLOCK semantic-attention (ticket pattern;
//           atomicExch read-and-reset keeps colsum zeroed for the next launch).
struct MS { const float* att[4]; float* out[4]; int nsc; };

template <int TANH, int RELUA, int COMBINE, int OUTH>
__global__ __launch_bounds__(256)
void sgemm_k(const float* __restrict__ A0, const float* __restrict__ A1,
             const float* __restrict__ attnp,
             const float* __restrict__ B, const float* __restrict__ bias,
             void* __restrict__ Cv, float* __restrict__ colsum, int M, int K,
             MS sc, const float* __restrict__ qvec, float* __restrict__ attn_out,
             int* __restrict__ ticket)
{
    __shared__ alignas(16) float As[16][136];
    __shared__ alignas(16) float Bs[16][136];

    const float* A = (TANH && blockIdx.y) ? A1 : A0;
    float* cs = TANH ? colsum + blockIdx.y * 128 : colsum;

    const int tid = threadIdx.x;
    const int lane = tid & 31;
    const int warp = tid >> 5;
    const int wm = warp & 3;
    const int wn = warp >> 2;
    const int g = lane >> 2;
    const int t = lane & 3;
    const int block_row = blockIdx.x * 128;

    const int a_row = tid >> 1;
    const int a_col = (tid & 1) * 8;
    const int b_row = tid >> 4;
    const int b_col = (tid & 15) * 8;

    float ca0 = 0.f, ca1 = 0.f;
    if constexpr (COMBINE) { ca0 = __ldg(&attnp[0]); ca1 = __ldg(&attnp[1]); }

    const int gr = block_row + a_row;
    const bool arow_ok = (gr < M);

    float4 d[2][8];
#pragma unroll
    for (int i = 0; i < 2; i++)
#pragma unroll
        for (int j = 0; j < 8; j++) d[i][j] = make_float4(0.f, 0.f, 0.f, 0.f);

    float4 av0, av1, bv0, bv1;

    auto loadA = [&](int k0, float4& o0, float4& o1) {
        o0 = make_float4(0.f, 0.f, 0.f, 0.f);
        o1 = o0;
        if (arow_ok) {
            o0 = *(const float4*)(A + (size_t)gr * K + k0 + a_col);
            o1 = *(const float4*)(A + (size_t)gr * K + k0 + a_col + 4);
            if constexpr (COMBINE) {
                float4 w0 = *(const float4*)(A1 + (size_t)gr * K + k0 + a_col);
                float4 w1 = *(const float4*)(A1 + (size_t)gr * K + k0 + a_col + 4);
                o0.x = ca0 * fmaxf(o0.x, 0.f) + ca1 * fmaxf(w0.x, 0.f);
                o0.y = ca0 * fmaxf(o0.y, 0.f) + ca1 * fmaxf(w0.y, 0.f);
                o0.z = ca0 * fmaxf(o0.z, 0.f) + ca1 * fmaxf(w0.z, 0.f);
                o0.w = ca0 * fmaxf(o0.w, 0.f) + ca1 * fmaxf(w0.w, 0.f);
                o1.x = ca0 * fmaxf(o1.x, 0.f) + ca1 * fmaxf(w1.x, 0.f);
                o1.y = ca0 * fmaxf(o1.y, 0.f) + ca1 * fmaxf(w1.y, 0.f);
                o1.z = ca0 * fmaxf(o1.z, 0.f) + ca1 * fmaxf(w1.z, 0.f);
                o1.w = ca0 * fmaxf(o1.w, 0.f) + ca1 * fmaxf(w1.w, 0.f);
            } else if constexpr (RELUA || TANH) {
                o0.x = fmaxf(o0.x, 0.f); o0.y = fmaxf(o0.y, 0.f);
                o0.z = fmaxf(o0.z, 0.f); o0.w = fmaxf(o0.w, 0.f);
                o1.x = fmaxf(o1.x, 0.f); o1.y = fmaxf(o1.y, 0.f);
                o1.z = fmaxf(o1.z, 0.f); o1.w = fmaxf(o1.w, 0.f);
            }
        }
    };

    loadA(0, av0, av1);
    bv0 = *(const float4*)(B + (size_t)b_row * 128 + b_col);
    bv1 = *(const float4*)(B + (size_t)b_row * 128 + b_col + 4);

    for (int k0 = 0; k0 < K; k0 += 16) {
        As[a_col + 0][a_row] = tfbits(av0.x);
        As[a_col + 1][a_row] = tfbits(av0.y);
        As[a_col + 2][a_row] = tfbits(av0.z);
        As[a_col + 3][a_row] = tfbits(av0.w);
        As[a_col + 4][a_row] = tfbits(av1.x);
        As[a_col + 5][a_row] = tfbits(av1.y);
        As[a_col + 6][a_row] = tfbits(av1.z);
        As[a_col + 7][a_row] = tfbits(av1.w);
        Bs[b_row][b_col + 0] = tfbits(bv0.x);
        Bs[b_row][b_col + 1] = tfbits(bv0.y);
        Bs[b_row][b_col + 2] = tfbits(bv0.z);
        Bs[b_row][b_col + 3] = tfbits(bv0.w);
        Bs[b_row][b_col + 4] = tfbits(bv1.x);
        Bs[b_row][b_col + 5] = tfbits(bv1.y);
        Bs[b_row][b_col + 6] = tfbits(bv1.z);
        Bs[b_row][b_col + 7] = tfbits(bv1.w);
        __syncthreads();

        if (k0 + 16 < K) {
            loadA(k0 + 16, av0, av1);
            bv0 = *(const float4*)(B + (size_t)(k0 + 16 + b_row) * 128 + b_col);
            bv1 = *(const float4*)(B + (size_t)(k0 + 16 + b_row) * 128 + b_col + 4);
        }

#pragma unroll
        for (int kk = 0; kk < 16; kk += 8) {
            unsigned au[2][4];
#pragma unroll
            for (int mi = 0; mi < 2; mi++) {
                const int rb = wm * 32 + mi * 16 + g;
                au[mi][0] = __float_as_uint(As[kk + t][rb]);
                au[mi][1] = __float_as_uint(As[kk + t][rb + 8]);
                au[mi][2] = __float_as_uint(As[kk + t + 4][rb]);
                au[mi][3] = __float_as_uint(As[kk + t + 4][rb + 8]);
            }
#pragma unroll
            for (int ni = 0; ni < 8; ni++) {
                const int nb = wn * 64 + ni * 8 + g;
                const unsigned b0 = __float_as_uint(Bs[kk + t][nb]);
                const unsigned b1 = __float_as_uint(Bs[kk + t + 4][nb]);
                mma_tf32(d[0][ni], au[0], b0, b1);
                mma_tf32(d[1][ni], au[1], b0, b1);
            }
        }
        __syncthreads();
    }

    float2 bb[8];
#pragma unroll
    for (int ni = 0; ni < 8; ni++) {
        const int c = wn * 64 + ni * 8 + t * 2;
        bb[ni] = make_float2(__ldg(&bias[c]), __ldg(&bias[c + 1]));
    }

    if constexpr (TANH) {
        __shared__ float red[128];
        if (tid < 128) red[tid] = 0.f;
        __syncthreads();
#pragma unroll
        for (int ni = 0; ni < 8; ni++) {
            const int c = wn * 64 + ni * 8 + t * 2;
            float sx = 0.f, sy = 0.f;
#pragma unroll
            for (int mi = 0; mi < 2; mi++) {
                const int r0 = block_row + wm * 32 + mi * 16 + g;
                const int r1 = r0 + 8;
                if (r0 < M) {
                    sx += tanhf(d[mi][ni].x + bb[ni].x);
                    sy += tanhf(d[mi][ni].y + bb[ni].y);
                }
                if (r1 < M) {
                    sx += tanhf(d[mi][ni].z + bb[ni].x);
                    sy += tanhf(d[mi][ni].w + bb[ni].y);
                }
            }
            atomicAdd(&red[c], sx);
            atomicAdd(&red[c + 1], sy);
        }
        __syncthreads();
        if (tid < 128) {
            atomicAdd(&cs[tid], red[tid]);
            __threadfence();   // colsum update visible before ticket increment
        }
        // -------- last-block semantic attention (fused sem_attn) --------
        __shared__ int lastFlag;
        __syncthreads();
        if (tid == 0) {
            const int nblk = (int)(gridDim.x * gridDim.y);
            const int tk = atomicAdd(ticket, 1);
            lastFlag = (tk == nblk - 1);
        }
        __syncthreads();
        if (lastFlag) {
            __shared__ float sr0[128], sr1[128];
            if (tid < 128) {
                const float v0 = atomicExch(&colsum[tid], 0.f);        // read+reset
                const float v1 = atomicExch(&colsum[128 + tid], 0.f);
                const float qv = __ldg(&qvec[tid]);
                sr0[tid] = qv * v0;
                sr1[tid] = qv * v1;
            }
            __syncthreads();
            for (int s = 64; s > 0; s >>= 1) {
                if (tid < s) { sr0[tid] += sr0[tid + s]; sr1[tid] += sr1[tid + s]; }
                __syncthreads();
            }
            if (tid == 0) {
                const float s0 = sr0[0] / (float)NP;
                const float s1 = sr1[0] / (float)NP;
                const float m = fmaxf(s0, s1);
                const float e0 = __expf(s0 - m), e1 = __expf(s1 - m);
                const float inv = 1.f / (e0 + e1);
                attn_out[0] = e0 * inv;
                attn_out[1] = e1 * inv;
                *ticket = 0;                                           // self-reset
            }
        }
    } else {
        // add bias in place (stores AND score epilogue use biased values)
#pragma unroll
        for (int mi = 0; mi < 2; mi++)
#pragma unroll
            for (int ni = 0; ni < 8; ni++) {
                d[mi][ni].x += bb[ni].x; d[mi][ni].y += bb[ni].y;
                d[mi][ni].z += bb[ni].x; d[mi][ni].w += bb[ni].y;
            }

        if constexpr (OUTH) {
            __half* C = (__half*)Cv;
#pragma unroll
            for (int mi = 0; mi < 2; mi++) {
                const int r0 = block_row + wm * 32 + mi * 16 + g;
                const int r1 = r0 + 8;
#pragma unroll
                for (int ni = 0; ni < 8; ni++) {
                    const int c = wn * 64 + ni * 8 + t * 2;
                    if (r0 < M)
                        *(__half2*)(C + (size_t)r0 * 128 + c) =
                            __floats2half2_rn(d[mi][ni].x, d[mi][ni].y);
                    if (r1 < M)
                        *(__half2*)(C + (size_t)r1 * 128 + c) =
                            __floats2half2_rn(d[mi][ni].z, d[mi][ni].w);
                }
            }
        } else {
            float* C = (float*)Cv;
#pragma unroll
            for (int mi = 0; mi < 2; mi++) {
                const int r0 = block_row + wm * 32 + mi * 16 + g;
                const int r1 = r0 + 8;
#pragma unroll
                for (int ni = 0; ni < 8; ni++) {
                    const int c = wn * 64 + ni * 8 + t * 2;
                    if (r0 < M)
                        *(float2*)(C + (size_t)r0 * 128 + c) =
                            make_float2(d[mi][ni].x, d[mi][ni].y);
                    if (r1 < M)
                        *(float2*)(C + (size_t)r1 * 128 + c) =
                            make_float2(d[mi][ni].z, d[mi][ni].w);
                }
            }
        }

        // -------- fused attention-score epilogue --------
        // score(row, head) = sum_{c in head} val[row][c]*att[c]; head = wn*4 + m.
        // Thread t covers 2 cols of each 8-col group; quad-reduce over t via shfl.
        for (int s = 0; s < sc.nsc; s++) {
            const float* av = sc.att[s];
            float* o = sc.out[s];
            float2 at[8];
#pragma unroll
            for (int ni = 0; ni < 8; ni++) {
                const int c = wn * 64 + ni * 8 + t * 2;
                at[ni] = *(const float2*)(av + c);
            }
#pragma unroll
            for (int mi = 0; mi < 2; mi++) {
                const int r0 = block_row + wm * 32 + mi * 16 + g;
                const int r1 = r0 + 8;
#pragma unroll
                for (int m = 0; m < 4; m++) {
                    float p0 = d[mi][2 * m].x * at[2 * m].x + d[mi][2 * m].y * at[2 * m].y
                             + d[mi][2 * m + 1].x * at[2 * m + 1].x
                             + d[mi][2 * m + 1].y * at[2 * m + 1].y;
                    float p1 = d[mi][2 * m].z * at[2 * m].x + d[mi][2 * m].w * at[2 * m].y
                             + d[mi][2 * m + 1].z * at[2 * m + 1].x
                             + d[mi][2 * m + 1].w * at[2 * m + 1].y;
                    p0 += __shfl_xor_sync(0xffffffffu, p0, 1);
                    p0 += __shfl_xor_sync(0xffffffffu, p0, 2);
                    p1 += __shfl_xor_sync(0xffffffffu, p1, 1);
                    p1 += __shfl_xor_sync(0xffffffffu, p1, 2);
                    if (t == 0) {
                        const int head = wn * 4 + m;
                        if (r0 < M) o[(size_t)r0 * 8 + head] = p0;
                        if (r1 < M) o[(size_t)r1 * 8 + head] = p1;
                    }
                }
            }
        }
    }
}

// ----------------------------- final linear (fused layer-1 combine + relu) ---------
__global__ __launch_bounds__(256)
void final_lin_k(const float* __restrict__ s0, const float* __restrict__ s1,
                 const float* __restrict__ attn, const float* __restrict__ W,
                 const float* __restrict__ b, float* __restrict__ out)
{
    __shared__ float Ws[128 * NCLS];
    for (int i = threadIdx.x; i < 128 * NCLS; i += blockDim.x) Ws[i] = W[i];
    __syncthreads();
    const int n = blockIdx.x * blockDim.x + threadIdx.x;
    if (n >= NP) return;
    const float a0 = __ldg(&attn[0]);
    const float a1 = __ldg(&attn[1]);
    float acc[NCLS];
#pragma unroll
    for (int c = 0; c < NCLS; c++) acc[c] = __ldg(&b[c]);
    const float4* x0 = (const float4*)(s0 + (size_t)n * 128);
    const float4* x1 = (const float4*)(s1 + (size_t)n * 128);
#pragma unroll
    for (int k4 = 0; k4 < 32; k4++) {
        float4 u = __ldg(&x0[k4]);
        float4 v = __ldg(&x1[k4]);
        const float xs[4] = {
            a0 * fmaxf(u.x, 0.f) + a1 * fmaxf(v.x, 0.f),
            a0 * fmaxf(u.y, 0.f) + a1 * fmaxf(v.y, 0.f),
            a0 * fmaxf(u.z, 0.f) + a1 * fmaxf(v.z, 0.f),
            a0 * fmaxf(u.w, 0.f) + a1 * fmaxf(v.w, 0.f)};
#pragma unroll
        for (int uu = 0; uu < 4; uu++) {
            const int k = k4 * 4 + uu;
#pragma unroll
            for (int c = 0; c < NCLS; c++)
                acc[c] = fmaf(xs[uu], Ws[k * NCLS + c], acc[c]);
        }
    }
    float4* op = (float4*)(out + (size_t)n * NCLS);
#pragma unroll
    for (int c4 = 0; c4 < 4; c4++)
        op[c4] = make_float4(acc[c4 * 4], acc[c4 * 4 + 1], acc[c4 * 4 + 2], acc[c4 * 4 + 3]);
}

// ----------------------------- host orchestration ----------------------------------
extern "C" void kernel_launch(void* const* d_in, const int* in_sizes, int n_in,
                              void* d_out, int out_size)
{
    const float* x_author = (const float*)d_in[0];
    const float* x_paper  = (const float*)d_in[1];
    const float* Wa       = (const float*)d_in[2];
    const float* proj_w   = (const float*)d_in[3];
    const float* proj_b   = (const float*)d_in[4];
    const float* att_src  = (const float*)d_in[5];
    const float* att_dst  = (const float*)d_in[6];
    const float* klin_w   = (const float*)d_in[7];
    const float* klin_b   = (const float*)d_in[8];
    const float* q        = (const float*)d_in[9];
    const float* lin_w    = (const float*)d_in[10];
    const float* lin_b    = (const float*)d_in[11];
    const int*   ei_w     = (const int*)d_in[12];
    const int*   ei_wb    = (const int*)d_in[13];
    const int*   ei_c     = (const int*)d_in[14];
    float* out = (float*)d_out;

    float *auth0, *aggA, *aggP0, *aggP1;
    __half *xa, *xp;
    float *sa0, *sa1, *sp0, *sp1, *sp2, *sp3, *colsum, *attn0, *attn1, *zb;
    int *ticket;
    int *rp_w, *rp_wb, *rp_c, *src_w, *src_wb, *src_c, *cnt, *aux;
    cudaGetSymbolAddress((void**)&auth0, g_auth0);
    cudaGetSymbolAddress((void**)&aggA, g_aggA);
    cudaGetSymbolAddress((void**)&xa, g_xa);
    cudaGetSymbolAddress((void**)&xp, g_xp);
    cudaGetSymbolAddress((void**)&aggP0, g_aggP0);
    cudaGetSymbolAddress((void**)&aggP1, g_aggP1);
    cudaGetSymbolAddress((void**)&sa0, g_sa0);
    cudaGetSymbolAddress((void**)&sa1, g_sa1);
    cudaGetSymbolAddress((void**)&sp0, g_sp0);
    cudaGetSymbolAddress((void**)&sp1, g_sp1);
    cudaGetSymbolAddress((void**)&sp2, g_sp2);
    cudaGetSymbolAddress((void**)&sp3, g_sp3);
    cudaGetSymbolAddress((void**)&colsum, g_colsum);
    cudaGetSymbolAddress((void**)&attn0, g_attn0);
    cudaGetSymbolAddress((void**)&attn1, g_attn1);
    cudaGetSymbolAddress((void**)&zb, g_zb);
    cudaGetSymbolAddress((void**)&ticket, g_ticket);
    cudaGetSymbolAddress((void**)&rp_w, g_rp_w);
    cudaGetSymbolAddress((void**)&rp_wb, g_rp_wb);
    cudaGetSymbolAddress((void**)&rp_c, g_rp_c);
    cudaGetSymbolAddress((void**)&src_w, g_src_w);
    cudaGetSymbolAddress((void**)&src_wb, g_src_wb);
    cudaGetSymbolAddress((void**)&src_c, g_src_c);
    cudaGetSymbolAddress((void**)&cnt, g_cnt);
    cudaGetSymbolAddress((void**)&aux, g_aux);

    int* cnt_w  = cnt;
    int* cnt_wb = cnt + NP;
    int* cnt_c  = cnt + NP + NA;
    int* aux_w  = aux;
    int* aux_wb = aux + 256;
    int* aux_c  = aux + 512;

    const int EB = (EE + 255) / 256;
    const int BW  = (NP + 255) / 256;
    const int BWB = (NA + 255) / 256;

    const MS noSc = {{nullptr, nullptr, nullptr, nullptr},
                     {nullptr, nullptr, nullptr, nullptr}, 0};

    // ---- CSR build ----
    cudaMemsetAsync(cnt, 0, (2 * NP + NA) * sizeof(int));
    {
        H3 h; h.dst[0] = ei_w + EE; h.dst[1] = ei_wb + EE; h.dst[2] = ei_c + EE;
        h.cnt[0] = cnt_w; h.cnt[1] = cnt_wb; h.cnt[2] = cnt_c;
        hist3_k<<<dim3(EB, 3), 256>>>(h);
    }
    {
        SC3 s;
        s.cnt[0] = cnt_w;  s.rowptr[0] = rp_w;  s.aux[0] = aux_w;  s.n[0] = NP;
        s.cnt[1] = cnt_wb; s.rowptr[1] = rp_wb; s.aux[1] = aux_wb; s.n[1] = NA;
        s.cnt[2] = cnt_c;  s.rowptr[2] = rp_c;  s.aux[2] = aux_c;  s.n[2] = NP;
        scan_blk3_k<<<dim3(BW, 3), 256>>>(s);
    }
    {
        SA3 s;
        s.aux[0] = aux_w; s.nb[0] = BW;
        s.aux[1] = aux_wb; s.nb[1] = BWB;
        s.aux[2] = aux_c; s.nb[2] = BW;
        scan_aux3_k<<<3, 256>>>(s);
    }
    {
        AD3 s;
        s.rowptr[0] = rp_w;  s.aux[0] = aux_w;  s.n[0] = NP;
        s.rowptr[1] = rp_wb; s.aux[1] = aux_wb; s.n[1] = NA;
        s.rowptr[2] = rp_c;  s.aux[2] = aux_c;  s.n[2] = NP;
        scan_add3_k<<<dim3(BW, 3), 256>>>(s);
    }
    cudaMemsetAsync(cnt, 0, (2 * NP + NA) * sizeof(int));
    {
        S3 s;
        s.ei[0] = ei_w;  s.rowptr[0] = rp_w;  s.cursor[0] = cnt_w;  s.srcs[0] = src_w;
        s.ei[1] = ei_wb; s.rowptr[1] = rp_wb; s.cursor[1] = cnt_wb; s.srcs[1] = src_wb;
        s.ei[2] = ei_c;  s.rowptr[2] = rp_c;  s.cursor[2] = cnt_c;  s.srcs[2] = src_c;
        scatter3_k<<<dim3(EB, 3), 256>>>(s);
    }

    // author raw projection: [20000,64] @ [64,128] (no bias, fp32 out)
    sgemm_k<0, 0, 0, 0><<<(NA + 127) / 128, 256>>>(
        x_author, nullptr, nullptr, Wa, zb, auth0, nullptr, NA, 64,
        noSc, nullptr, nullptr, nullptr);

    // =============================== layer 0 ===============================
    {   // author projection + scores (writes-src, written_by-dst)
        MS ms = {{att_src + 0 * 128, att_dst + 1 * 128, nullptr, nullptr},
                 {sa0, sa1, nullptr, nullptr}, 2};
        sgemm_k<0, 0, 0, 1><<<(NA + 127) / 128, 256>>>(
            auth0, nullptr, nullptr, proj_w, proj_b, xa, nullptr, NA, 128,
            ms, nullptr, nullptr, nullptr);
    }
    {   // paper projection + scores (writes-dst, wb-src, cites-src, cites-dst)
        MS ms = {{att_dst + 0 * 128, att_src + 1 * 128, att_src + 2 * 128, att_dst + 2 * 128},
                 {sp0, sp1, sp2, sp3}, 4};
        sgemm_k<0, 0, 0, 1><<<(NP + 127) / 128, 256>>>(
            x_paper, nullptr, nullptr, proj_w + (size_t)128 * 128, proj_b + 128,
            xp, nullptr, NP, 128, ms, nullptr, nullptr, nullptr);
    }

    // SEQUENTIAL aggregations (L2-resident working sets)
    agg_csr_k<<<(NP * 32 + 255) / 256, 256>>>(rp_w,  src_w,  sa0, sp0, xa, aggP0, NP);
    agg_csr_k<<<(NA * 32 + 255) / 256, 256>>>(rp_wb, src_wb, sp1, sa1, xp, aggA,  NA);
    agg_csr_k<<<(NP * 32 + 255) / 256, 256>>>(rp_c,  src_c,  sp2, sp3, xp, aggP1, NP);

    // tanh-GEMM with fused last-block semantic attention (no memset, no sem launch)
    sgemm_k<1, 1, 0, 0><<<dim3((NP + 127) / 128, 2), 256>>>(
        aggP0, aggP1, nullptr, klin_w, klin_b, nullptr, colsum, NP, 128,
        noSc, q, attn0, ticket);

    // =============================== layer 1 ===============================
    {   // author projection (relu fused) + score (writes-src)
        MS ms = {{att_src + 3 * 128, nullptr, nullptr, nullptr},
                 {sa0, nullptr, nullptr, nullptr}, 1};
        sgemm_k<0, 1, 0, 1><<<(NA + 127) / 128, 256>>>(
            aggA, nullptr, nullptr, proj_w + (size_t)2 * 128 * 128, proj_b + 2 * 128,
            xa, nullptr, NA, 128, ms, nullptr, nullptr, nullptr);
    }
    {   // paper projection (layer-0 combine fused) + scores (writes-dst, cites-src/dst)
        MS ms = {{att_dst + 3 * 128, att_src + 5 * 128, att_dst + 5 * 128, nullptr},
                 {sp0, sp2, sp3, nullptr}, 3};
        sgemm_k<0, 0, 1, 1><<<(NP + 127) / 128, 256>>>(
            aggP0, aggP1, attn0, proj_w + (size_t)3 * 128 * 128, proj_b + 3 * 128,
            xp, nullptr, NP, 128, ms, nullptr, nullptr, nullptr);
    }

    agg_csr_k<<<(NP * 32 + 255) / 256, 256>>>(rp_w, src_w, sa0, sp0, xa, aggP0, NP);
    agg_csr_k<<<(NP * 32 + 255) / 256, 256>>>(rp_c, src_c, sp2, sp3, xp, aggP1, NP);

    sgemm_k<1, 1, 0, 0><<<dim3((NP + 127) / 128, 2), 256>>>(
        aggP0, aggP1, nullptr, klin_w + (size_t)128 * 128, klin_b + 128,
        nullptr, colsum, NP, 128, noSc, q + 128, attn1, ticket);

    final_lin_k<<<(NP + 255) / 256, 256>>>(aggP0, aggP1, attn1, lin_w, lin_b, out);
}